// round 2
// baseline (speedup 1.0000x reference)
#include <cuda_runtime.h>

#define N_NODES 200000
#define N_VAR   112000
#define N_EDGES 3200000
#define HID     64
#define CAP     64      // max in-degree bucket (Poisson(16): P(deg>64) ~ 1e-18)

// ---- scratch: __device__ globals (referenced ONLY from device code) ----
__device__ int   d_cnt[N_NODES];
__device__ int   d_col[(size_t)N_NODES * CAP];
__device__ float d_dinv[N_NODES];
__device__ float d_bufA[(size_t)N_NODES * HID];   // g1 = (x@W1)*dinv
__device__ float d_bufB[(size_t)N_NODES * HID];   // g2 = (relu(agg1)@W2)*dinv

__global__ void k_zero() {
    int i = blockIdx.x * blockDim.x + threadIdx.x;
    if (i < N_NODES) d_cnt[i] = 0;
}

// bucket edges by destination: one int atomic per edge
__global__ void k_fill(const int* __restrict__ ei) {
    int e = blockIdx.x * blockDim.x + threadIdx.x;
    if (e >= N_EDGES) return;
    int s = ei[e];               // src
    int d = ei[N_EDGES + e];     // dst
    int p = atomicAdd(&d_cnt[d], 1);
    if (p < CAP) d_col[(size_t)d * CAP + p] = s;
}

// per node: dinv and g1 = (x @ W1) * dinv   (one float4 of output per thread)
__global__ void k_g1(const float2* __restrict__ x, const float* __restrict__ W1) {
    int idx = blockIdx.x * blockDim.x + threadIdx.x;   // N_NODES*16 threads
    if (idx >= N_NODES * 16) return;
    int n = idx >> 4, q = idx & 15;
    float di = rsqrtf((float)d_cnt[n] + 1.0f);
    if (q == 0) d_dinv[n] = di;
    float2 xv = __ldg(&x[n]);
    const float4* W1v = (const float4*)W1;   // [2,64] row-major
    float4 w0 = __ldg(&W1v[q]);
    float4 w1 = __ldg(&W1v[16 + q]);
    float4 g;
    g.x = (xv.x * w0.x + xv.y * w1.x) * di;
    g.y = (xv.x * w0.y + xv.y * w1.y) * di;
    g.z = (xv.x * w0.z + xv.y * w1.z) * di;
    g.w = (xv.x * w0.w + xv.y * w1.w) * di;
    ((float4*)d_bufA)[idx] = g;
}

// fused aggregate + dense 64x64 matmul
// LAST=false: r = relu(dinv*(sum g1[src] + g1[n]) + b1);  d_bufB = dinv * (r @ W2)
// LAST=true : a = dinv*(sum g2[src] + g2[n]) + b2;        out    = rint(relu(a @ Wfc + bfc))
template <bool LAST>
__global__ void k_agg(float* __restrict__ gout_ext,
                      const float* __restrict__ bias_pre,
                      const float* __restrict__ Wm,
                      const float* __restrict__ bias_post) {
    const float* __restrict__ gin = LAST ? d_bufB : d_bufA;   // device-side symbol ref
    float* __restrict__ gout      = LAST ? gout_ext : d_bufB;

    __shared__ float sW[HID * HID];   // 16 KB weights
    __shared__ float sR[8][HID];      // aggregated rows, one per warp

    int tid = threadIdx.x;            // 256 threads, 8 warps = 8 nodes/block
    for (int i = tid; i < HID * HID / 4; i += 256)
        ((float4*)sW)[i] = ((const float4*)Wm)[i];

    int warp = tid >> 5, lane = tid & 31;
    int n = blockIdx.x * 8 + warp;
    const int NLIM = LAST ? N_VAR : N_NODES;

    float di = 0.0f;
    if (n < NLIM) {
        int deg = d_cnt[n];
        if (deg > CAP) deg = CAP;
        const int* cl = &d_col[(size_t)n * CAP];
        float a0 = 0.0f, a1 = 0.0f;
        int e = 0;
        for (; e + 3 < deg; e += 4) {            // 8 independent LDGs in flight
            int s0 = cl[e], s1 = cl[e + 1], s2 = cl[e + 2], s3 = cl[e + 3];
            const float* p0 = gin + (size_t)s0 * HID;
            const float* p1 = gin + (size_t)s1 * HID;
            const float* p2 = gin + (size_t)s2 * HID;
            const float* p3 = gin + (size_t)s3 * HID;
            float v00 = p0[lane], v01 = p0[lane + 32];
            float v10 = p1[lane], v11 = p1[lane + 32];
            float v20 = p2[lane], v21 = p2[lane + 32];
            float v30 = p3[lane], v31 = p3[lane + 32];
            a0 += (v00 + v10) + (v20 + v30);
            a1 += (v01 + v11) + (v21 + v31);
        }
        for (; e < deg; e++) {
            const float* p0 = gin + (size_t)cl[e] * HID;
            a0 += p0[lane];
            a1 += p0[lane + 32];
        }
        const float* gn = gin + (size_t)n * HID;   // self-loop
        a0 += gn[lane];
        a1 += gn[lane + 32];
        di = d_dinv[n];
        a0 = a0 * di + bias_pre[lane];
        a1 = a1 * di + bias_pre[lane + 32];
        if (!LAST) { a0 = fmaxf(a0, 0.0f); a1 = fmaxf(a1, 0.0f); }
        sR[warp][lane]      = a0;
        sR[warp][lane + 32] = a1;
    }
    __syncthreads();
    if (n >= NLIM) return;

    float o0 = 0.0f, o1 = 0.0f;
#pragma unroll
    for (int k = 0; k < HID; k++) {
        float rk = sR[warp][k];
        o0 += rk * sW[k * HID + lane];
        o1 += rk * sW[k * HID + lane + 32];
    }
    size_t ob = (size_t)n * HID;
    if (LAST) {
        o0 = rintf(fmaxf(o0 + bias_post[lane],      0.0f));  // round-half-even == jnp.round
        o1 = rintf(fmaxf(o1 + bias_post[lane + 32], 0.0f));
    } else {
        o0 *= di;
        o1 *= di;
    }
    gout[ob + lane]      = o0;
    gout[ob + lane + 32] = o1;
}

extern "C" void kernel_launch(void* const* d_in, const int* in_sizes, int n_in,
                              void* d_out, int out_size) {
    const float* x   = (const float*)d_in[0];   // [200000, 2]
    const int*   ei  = (const int*)d_in[1];     // [2, 3200000]
    const float* W1  = (const float*)d_in[2];   // [2, 64]
    const float* b1  = (const float*)d_in[3];   // [64]
    const float* W2  = (const float*)d_in[4];   // [64, 64]
    const float* b2  = (const float*)d_in[5];   // [64]
    const float* Wfc = (const float*)d_in[6];   // [64, 64]
    const float* bfc = (const float*)d_in[7];   // [64]
    float* out = (float*)d_out;                 // [112000*64] flat

    k_zero<<<(N_NODES + 255) / 256, 256>>>();
    k_fill<<<(N_EDGES + 255) / 256, 256>>>(ei);
    k_g1<<<(N_NODES * 16 + 255) / 256, 256>>>((const float2*)x, W1);
    k_agg<false><<<N_NODES / 8, 256>>>(nullptr, b1, W2, nullptr);
    k_agg<true><<<N_VAR / 8, 256>>>(out, b2, Wfc, bfc);
}

// round 5
// speedup vs baseline: 1.4865x; 1.4865x over previous
#include <cuda_runtime.h>

#define N_NODES 200000
#define N_VAR   112000
#define N_EDGES 3200000
#define HID     64
#define CAP     64      // max in-degree bucket (Poisson(16): P(deg>64) ~ 1e-18)
#define PAD     72      // smem row stride: 16B-aligned (72*4=288)

// ---- scratch: __device__ globals (referenced ONLY from device code) ----
__device__ int    d_cnt[N_NODES];
__device__ int    d_col[(size_t)N_NODES * CAP];
__device__ float  d_dinv[N_NODES];
__device__ float2 d_pg[N_NODES];                     // x[n] * dinv[n]
__device__ float2 d_A1[N_NODES];                     // layer-1 aggregated 2-wide features
__device__ float  d_g1[(size_t)N_NODES * HID];       // relu(A1@W1+b1)*dinv
__device__ float  d_Wc[HID * HID + HID];             // W2@Wfc, then bc = b2@Wfc+bfc

__global__ void k_zero() {
    int i = blockIdx.x * blockDim.x + threadIdx.x;
    if (i < N_NODES) d_cnt[i] = 0;
}

// bucket edges by destination: one int atomic per edge
__global__ void k_fill(const int* __restrict__ ei) {
    int e = blockIdx.x * blockDim.x + threadIdx.x;
    if (e >= N_EDGES) return;
    int s = ei[e];
    int d = ei[N_EDGES + e];
    int p = atomicAdd(&d_cnt[d], 1);
    if (p < CAP) d_col[d * CAP + p] = s;
}

// precompute Wc = W2 @ Wfc and bc = b2 @ Wfc + bfc
__global__ void k_wc(const float* __restrict__ W2, const float* __restrict__ b2,
                     const float* __restrict__ Wfc, const float* __restrict__ bfc) {
    int t = blockIdx.x * blockDim.x + threadIdx.x;
    if (t < HID * HID) {
        int k = t >> 6, c = t & 63;
        float o = 0.0f;
#pragma unroll 16
        for (int j = 0; j < HID; j++) o += W2[k * HID + j] * Wfc[j * HID + c];
        d_Wc[t] = o;
    } else if (t < HID * HID + HID) {
        int c = t - HID * HID;
        float o = bfc[c];
#pragma unroll 16
        for (int j = 0; j < HID; j++) o += b2[j] * Wfc[j * HID + c];
        d_Wc[HID * HID + c] = o;
    }
}

// per node: dinv and pg = x * dinv
__global__ void k_prep(const float2* __restrict__ x) {
    int n = blockIdx.x * blockDim.x + threadIdx.x;
    if (n >= N_NODES) return;
    float di = rsqrtf((float)d_cnt[n] + 1.0f);
    d_dinv[n] = di;
    float2 xv = __ldg(&x[n]);
    d_pg[n] = make_float2(xv.x * di, xv.y * di);
}

// layer-1 aggregation on raw 2-wide features: A1 = dinv*(sum pg[src] + pg[n])
// (self-loop in reference = h[n]*dinv^2 = pg[n]*dinv  -> inside the parens it is just pg[n])
__global__ void k_agg1() {
    int n = blockIdx.x * blockDim.x + threadIdx.x;
    if (n >= N_NODES) return;
    int deg = d_cnt[n];
    if (deg > CAP) deg = CAP;
    const int* cl = &d_col[n * CAP];
    float ax = 0.0f, ay = 0.0f;
    int e = 0;
    for (; e + 4 <= deg; e += 4) {
        int4 ii = *(const int4*)&cl[e];          // 16B aligned (CAP and e%4==0)
        float2 p0 = d_pg[ii.x], p1 = d_pg[ii.y], p2 = d_pg[ii.z], p3 = d_pg[ii.w];
        ax += (p0.x + p1.x) + (p2.x + p3.x);
        ay += (p0.y + p1.y) + (p2.y + p3.y);
    }
    for (; e < deg; e++) {
        float2 p = d_pg[cl[e]];
        ax += p.x; ay += p.y;
    }
    float di = d_dinv[n];
    float2 pn = d_pg[n];
    ax = di * (ax + pn.x);       // FIXED: was di*(ax + pn.x*di) — extra dinv on self term
    ay = di * (ay + pn.y);
    d_A1[n] = make_float2(ax, ay);
}

// g1 = relu(A1 @ W1 + b1) * dinv   (one float4 of output per thread)
__global__ void k_h1(const float* __restrict__ W1, const float* __restrict__ b1) {
    int idx = blockIdx.x * blockDim.x + threadIdx.x;  // N_NODES*16 threads
    if (idx >= N_NODES * 16) return;
    int n = idx >> 4, q = idx & 15;
    float2 A = d_A1[n];
    float di = d_dinv[n];
    const float4* W1v = (const float4*)W1;   // [2,64] row-major
    float4 w0 = __ldg(&W1v[q]);
    float4 w1 = __ldg(&W1v[16 + q]);
    float4 bv = __ldg(&((const float4*)b1)[q]);
    float4 g;
    g.x = fmaxf(A.x * w0.x + A.y * w1.x + bv.x, 0.0f) * di;
    g.y = fmaxf(A.x * w0.y + A.y * w1.y + bv.y, 0.0f) * di;
    g.z = fmaxf(A.x * w0.z + A.y * w1.z + bv.z, 0.0f) * di;
    g.w = fmaxf(A.x * w0.w + A.y * w1.w + bv.w, 0.0f) * di;
    ((float4*)d_g1)[idx] = g;
}

// layer-2 aggregation (only N_VAR nodes) + fused matmul with Wc + relu + rint
__global__ void __launch_bounds__(256) k_agg2(float* __restrict__ out) {
    __shared__ float sWT[HID][PAD];  // transposed Wc, 16B-aligned rows
    __shared__ float sR[8][PAD];     // aggregated rows
    __shared__ float sOut[8][PAD];   // staged outputs for coalesced store
    __shared__ float sBc[HID];

    int tid = threadIdx.x;           // 256 threads, 8 warps = 8 nodes/block
    for (int i = tid; i < HID * HID; i += 256) {
        int k = i >> 6, c = i & 63;
        sWT[c][k] = d_Wc[i];
    }
    if (tid < HID) sBc[tid] = d_Wc[HID * HID + tid];

    int warp = tid >> 5, lane = tid & 31;
    int n = blockIdx.x * 8 + warp;

    {
        int deg = d_cnt[n];
        if (deg > CAP) deg = CAP;
        const int* cl = &d_col[n * CAP];
        int idx0 = cl[lane];             // coalesced index loads (all CAP slots exist)
        int idx1 = cl[lane + 32];
        const float* __restrict__ g1 = d_g1;
        float a0 = 0.0f, a1 = 0.0f;
        int e = 0;
        for (; e + 4 <= deg; e += 4) {   // 8 independent LDGs in flight
            int hsel = (e < 32) ? idx0 : idx1;
            int s0 = __shfl_sync(0xffffffffu, hsel, e & 31);
            int s1 = __shfl_sync(0xffffffffu, hsel, (e & 31) + 1);
            int s2 = __shfl_sync(0xffffffffu, hsel, (e & 31) + 2);
            int s3 = __shfl_sync(0xffffffffu, hsel, (e & 31) + 3);
            const float* p0 = g1 + (size_t)s0 * HID;
            const float* p1 = g1 + (size_t)s1 * HID;
            const float* p2 = g1 + (size_t)s2 * HID;
            const float* p3 = g1 + (size_t)s3 * HID;
            float v00 = p0[lane], v01 = p0[lane + 32];
            float v10 = p1[lane], v11 = p1[lane + 32];
            float v20 = p2[lane], v21 = p2[lane + 32];
            float v30 = p3[lane], v31 = p3[lane + 32];
            a0 += (v00 + v10) + (v20 + v30);
            a1 += (v01 + v11) + (v21 + v31);
        }
        for (; e < deg; e++) {
            int hsel = (e < 32) ? idx0 : idx1;
            int s = __shfl_sync(0xffffffffu, hsel, e & 31);
            const float* p = g1 + (size_t)s * HID;
            a0 += p[lane];
            a1 += p[lane + 32];
        }
        const float* gn = g1 + (size_t)n * HID;   // self-loop: g[n], then *di
        a0 += gn[lane];
        a1 += gn[lane + 32];
        float di = d_dinv[n];
        sR[warp][lane]      = a0 * di;
        sR[warp][lane + 32] = a1 * di;
    }
    __syncthreads();

    // matmul remap: thread -> (m = tid&7 node-in-block, c = tid>>3 column)
    {
        int m = tid & 7, c = tid >> 3;
        float o0 = 0.0f, o1 = 0.0f;
#pragma unroll
        for (int k = 0; k < HID; k += 4) {
            float4 r  = *(const float4*)&sR[m][k];       // 288B row stride: aligned
            float4 wA = *(const float4*)&sWT[c][k];
            float4 wB = *(const float4*)&sWT[c + 32][k];
            o0 += r.x * wA.x + r.y * wA.y + r.z * wA.z + r.w * wA.w;
            o1 += r.x * wB.x + r.y * wB.y + r.z * wB.z + r.w * wB.w;
        }
        o0 = rintf(fmaxf(o0 + sBc[c],      0.0f));   // round-half-even == jnp.round
        o1 = rintf(fmaxf(o1 + sBc[c + 32], 0.0f));
        sOut[m][c]      = o0;
        sOut[m][c + 32] = o1;
    }
    __syncthreads();

    out[(size_t)n * HID + lane]      = sOut[warp][lane];
    out[(size_t)n * HID + lane + 32] = sOut[warp][lane + 32];
}

extern "C" void kernel_launch(void* const* d_in, const int* in_sizes, int n_in,
                              void* d_out, int out_size) {
    const float* x   = (const float*)d_in[0];   // [200000, 2]
    const int*   ei  = (const int*)d_in[1];     // [2, 3200000]
    const float* W1  = (const float*)d_in[2];   // [2, 64]
    const float* b1  = (const float*)d_in[3];   // [64]
    const float* W2  = (const float*)d_in[4];   // [64, 64]
    const float* b2  = (const float*)d_in[5];   // [64]
    const float* Wfc = (const float*)d_in[6];   // [64, 64]
    const float* bfc = (const float*)d_in[7];   // [64]
    float* out = (float*)d_out;                 // [112000*64] flat

    k_wc<<<(HID * HID + HID + 255) / 256, 256>>>(W2, b2, Wfc, bfc);
    k_zero<<<(N_NODES + 255) / 256, 256>>>();
    k_fill<<<(N_EDGES + 255) / 256, 256>>>(ei);
    k_prep<<<(N_NODES + 255) / 256, 256>>>((const float2*)x);
    k_agg1<<<(N_NODES + 255) / 256, 256>>>();
    k_h1<<<(N_NODES * 16 + 255) / 256, 256>>>(W1, b1);
    k_agg2<<<N_VAR / 8, 256>>>(out);
}

// round 6
// speedup vs baseline: 1.9096x; 1.2846x over previous
#include <cuda_runtime.h>

#define N_NODES 200000
#define N_VAR   112000
#define N_EDGES 3200000
#define HID     64
#define CAP     64      // max in-degree bucket (Poisson(16): P(deg>64) ~ 1e-18)
#define PAD     76      // smem row stride: 304B, 16B-aligned, 12m%32 distinct for m=0..7

// ---- scratch: __device__ globals (referenced ONLY from device code) ----
__device__ int    d_cnt[N_NODES];
__device__ int    d_col[(size_t)N_NODES * CAP];
__device__ float  d_dinv[N_NODES];
__device__ float2 d_pg[N_NODES];                     // x[n] * dinv[n]
__device__ float2 d_A1[N_NODES];                     // layer-1 aggregated 2-wide features
__device__ float  d_g1[(size_t)N_NODES * HID];       // relu(A1@W1+b1)*dinv
__device__ float  d_Wc[HID * HID + HID];             // W2@Wfc, then bc = b2@Wfc+bfc

__global__ void k_zero() {
    int i = blockIdx.x * blockDim.x + threadIdx.x;
    if (i < N_NODES) d_cnt[i] = 0;
}

// bucket edges by destination: one int atomic per edge
__global__ void k_fill(const int* __restrict__ ei) {
    int e = blockIdx.x * blockDim.x + threadIdx.x;
    if (e >= N_EDGES) return;
    int s = ei[e];
    int d = ei[N_EDGES + e];
    int p = atomicAdd(&d_cnt[d], 1);
    if (p < CAP) d_col[d * CAP + p] = s;
}

// precompute Wc = W2 @ Wfc and bc = b2 @ Wfc + bfc
__global__ void k_wc(const float* __restrict__ W2, const float* __restrict__ b2,
                     const float* __restrict__ Wfc, const float* __restrict__ bfc) {
    int t = blockIdx.x * blockDim.x + threadIdx.x;
    if (t < HID * HID) {
        int k = t >> 6, c = t & 63;
        float o = 0.0f;
#pragma unroll 16
        for (int j = 0; j < HID; j++) o += W2[k * HID + j] * Wfc[j * HID + c];
        d_Wc[t] = o;
    } else if (t < HID * HID + HID) {
        int c = t - HID * HID;
        float o = bfc[c];
#pragma unroll 16
        for (int j = 0; j < HID; j++) o += b2[j] * Wfc[j * HID + c];
        d_Wc[HID * HID + c] = o;
    }
}

// per node: dinv and pg = x * dinv
__global__ void k_prep(const float2* __restrict__ x) {
    int n = blockIdx.x * blockDim.x + threadIdx.x;
    if (n >= N_NODES) return;
    float di = rsqrtf((float)d_cnt[n] + 1.0f);
    d_dinv[n] = di;
    float2 xv = __ldg(&x[n]);
    d_pg[n] = make_float2(xv.x * di, xv.y * di);
}

// layer-1 aggregation on raw 2-wide features: A1 = dinv*(sum pg[src] + pg[n])
__global__ void k_agg1() {
    int n = blockIdx.x * blockDim.x + threadIdx.x;
    if (n >= N_NODES) return;
    int deg = d_cnt[n];
    if (deg > CAP) deg = CAP;
    const int* cl = &d_col[n * CAP];
    float ax = 0.0f, ay = 0.0f;
    int e = 0;
    for (; e + 4 <= deg; e += 4) {
        int4 ii = *(const int4*)&cl[e];
        float2 p0 = d_pg[ii.x], p1 = d_pg[ii.y], p2 = d_pg[ii.z], p3 = d_pg[ii.w];
        ax += (p0.x + p1.x) + (p2.x + p3.x);
        ay += (p0.y + p1.y) + (p2.y + p3.y);
    }
    for (; e < deg; e++) {
        float2 p = d_pg[cl[e]];
        ax += p.x; ay += p.y;
    }
    float di = d_dinv[n];
    float2 pn = d_pg[n];
    ax = di * (ax + pn.x);
    ay = di * (ay + pn.y);
    d_A1[n] = make_float2(ax, ay);
}

// g1 = relu(A1 @ W1 + b1) * dinv
__global__ void k_h1(const float* __restrict__ W1, const float* __restrict__ b1) {
    int idx = blockIdx.x * blockDim.x + threadIdx.x;
    if (idx >= N_NODES * 16) return;
    int n = idx >> 4, q = idx & 15;
    float2 A = d_A1[n];
    float di = d_dinv[n];
    const float4* W1v = (const float4*)W1;
    float4 w0 = __ldg(&W1v[q]);
    float4 w1 = __ldg(&W1v[16 + q]);
    float4 bv = __ldg(&((const float4*)b1)[q]);
    float4 g;
    g.x = fmaxf(A.x * w0.x + A.y * w1.x + bv.x, 0.0f) * di;
    g.y = fmaxf(A.x * w0.y + A.y * w1.y + bv.y, 0.0f) * di;
    g.z = fmaxf(A.x * w0.z + A.y * w1.z + bv.z, 0.0f) * di;
    g.w = fmaxf(A.x * w0.w + A.y * w1.w + bv.w, 0.0f) * di;
    ((float4*)d_g1)[idx] = g;
}

// layer-2 aggregation (16 nodes/block) + fused 2x2-register-blocked matmul
__global__ void __launch_bounds__(256) k_agg2(float* __restrict__ out) {
    __shared__ float sWT[HID][PAD];  // transposed Wc
    __shared__ float sR[16][PAD];    // aggregated rows
    __shared__ float sOut[16][PAD];  // staged outputs
    __shared__ float sBc[HID];

    int tid = threadIdx.x;           // 256 threads, 8 warps, 16 nodes/block
    for (int i = tid; i < HID * HID; i += 256) {
        int k = i >> 6, c = i & 63;
        sWT[c][k] = d_Wc[i];
    }
    if (tid < HID) sBc[tid] = d_Wc[HID * HID + tid];

    int warp = tid >> 5, lane = tid & 31;
    const float* __restrict__ g1 = d_g1;

#pragma unroll
    for (int rep = 0; rep < 2; rep++) {
        int nl = warp * 2 + rep;                 // 0..15
        int n  = blockIdx.x * 16 + nl;
        int deg = d_cnt[n];
        if (deg > CAP) deg = CAP;
        const int* cl = &d_col[n * CAP];
        int idx0 = cl[lane];                     // coalesced (all CAP slots exist)
        int idx1 = cl[lane + 32];
        float a0 = 0.0f, a1 = 0.0f;
        int e = 0;
        for (; e + 8 <= deg; e += 8) {           // 16 independent LDGs in flight
            int hsel = (e < 32) ? idx0 : idx1;   // 8 | 32 -> whole group same half
            int b = e & 31;
            int s0 = __shfl_sync(0xffffffffu, hsel, b);
            int s1 = __shfl_sync(0xffffffffu, hsel, b + 1);
            int s2 = __shfl_sync(0xffffffffu, hsel, b + 2);
            int s3 = __shfl_sync(0xffffffffu, hsel, b + 3);
            int s4 = __shfl_sync(0xffffffffu, hsel, b + 4);
            int s5 = __shfl_sync(0xffffffffu, hsel, b + 5);
            int s6 = __shfl_sync(0xffffffffu, hsel, b + 6);
            int s7 = __shfl_sync(0xffffffffu, hsel, b + 7);
            const float* p0 = g1 + (size_t)s0 * HID;
            const float* p1 = g1 + (size_t)s1 * HID;
            const float* p2 = g1 + (size_t)s2 * HID;
            const float* p3 = g1 + (size_t)s3 * HID;
            const float* p4 = g1 + (size_t)s4 * HID;
            const float* p5 = g1 + (size_t)s5 * HID;
            const float* p6 = g1 + (size_t)s6 * HID;
            const float* p7 = g1 + (size_t)s7 * HID;
            float v0a = p0[lane], v0b = p0[lane + 32];
            float v1a = p1[lane], v1b = p1[lane + 32];
            float v2a = p2[lane], v2b = p2[lane + 32];
            float v3a = p3[lane], v3b = p3[lane + 32];
            float v4a = p4[lane], v4b = p4[lane + 32];
            float v5a = p5[lane], v5b = p5[lane + 32];
            float v6a = p6[lane], v6b = p6[lane + 32];
            float v7a = p7[lane], v7b = p7[lane + 32];
            a0 += ((v0a + v1a) + (v2a + v3a)) + ((v4a + v5a) + (v6a + v7a));
            a1 += ((v0b + v1b) + (v2b + v3b)) + ((v4b + v5b) + (v6b + v7b));
        }
        for (; e < deg; e++) {
            int hsel = (e < 32) ? idx0 : idx1;
            int s = __shfl_sync(0xffffffffu, hsel, e & 31);
            const float* p = g1 + (size_t)s * HID;
            a0 += p[lane];
            a1 += p[lane + 32];
        }
        const float* gn = g1 + (size_t)n * HID;   // self-loop
        a0 += gn[lane];
        a1 += gn[lane + 32];
        float di = d_dinv[n];
        sR[nl][lane]      = a0 * di;
        sR[nl][lane + 32] = a1 * di;
    }
    __syncthreads();

    // matmul: thread -> (m = tid&7 and m+8, c = tid>>3 and c+32): 2x2 outputs
    {
        int m = tid & 7, c = tid >> 3;
        float o00 = 0.0f, o01 = 0.0f, o10 = 0.0f, o11 = 0.0f;
#pragma unroll
        for (int k = 0; k < HID; k += 4) {
            float4 r0 = *(const float4*)&sR[m][k];       // conflict-free (PAD=76)
            float4 r1 = *(const float4*)&sR[m + 8][k];
            float4 wA = *(const float4*)&sWT[c][k];
            float4 wB = *(const float4*)&sWT[c + 32][k];
            o00 += r0.x * wA.x + r0.y * wA.y + r0.z * wA.z + r0.w * wA.w;
            o01 += r0.x * wB.x + r0.y * wB.y + r0.z * wB.z + r0.w * wB.w;
            o10 += r1.x * wA.x + r1.y * wA.y + r1.z * wA.z + r1.w * wA.w;
            o11 += r1.x * wB.x + r1.y * wB.y + r1.z * wB.z + r1.w * wB.w;
        }
        float bA = sBc[c], bB = sBc[c + 32];
        sOut[m][c]           = rintf(fmaxf(o00 + bA, 0.0f));   // round-half-even == jnp.round
        sOut[m][c + 32]      = rintf(fmaxf(o01 + bB, 0.0f));
        sOut[m + 8][c]       = rintf(fmaxf(o10 + bA, 0.0f));
        sOut[m + 8][c + 32]  = rintf(fmaxf(o11 + bB, 0.0f));
    }
    __syncthreads();

#pragma unroll
    for (int rep = 0; rep < 2; rep++) {
        int nl = warp * 2 + rep;
        size_t ob = ((size_t)blockIdx.x * 16 + nl) * HID;
        out[ob + lane]      = sOut[nl][lane];
        out[ob + lane + 32] = sOut[nl][lane + 32];
    }
}

extern "C" void kernel_launch(void* const* d_in, const int* in_sizes, int n_in,
                              void* d_out, int out_size) {
    const float* x   = (const float*)d_in[0];   // [200000, 2]
    const int*   ei  = (const int*)d_in[1];     // [2, 3200000]
    const float* W1  = (const float*)d_in[2];   // [2, 64]
    const float* b1  = (const float*)d_in[3];   // [64]
    const float* W2  = (const float*)d_in[4];   // [64, 64]
    const float* b2  = (const float*)d_in[5];   // [64]
    const float* Wfc = (const float*)d_in[6];   // [64, 64]
    const float* bfc = (const float*)d_in[7];   // [64]
    float* out = (float*)d_out;                 // [112000*64] flat

    k_wc<<<(HID * HID + HID + 255) / 256, 256>>>(W2, b2, Wfc, bfc);
    k_zero<<<(N_NODES + 255) / 256, 256>>>();
    k_fill<<<(N_EDGES + 255) / 256, 256>>>(ei);
    k_prep<<<(N_NODES + 255) / 256, 256>>>((const float2*)x);
    k_agg1<<<(N_NODES + 255) / 256, 256>>>();
    k_h1<<<(N_NODES * 16 + 255) / 256, 256>>>(W1, b1);
    k_agg2<<<N_VAR / 16, 256>>>(out);
}

// round 7
// speedup vs baseline: 2.1652x; 1.1338x over previous
#include <cuda_runtime.h>

#define N_NODES 200000
#define N_VAR   112000
#define N_EDGES 3200000
#define HID     64
#define CAP     64      // max in-degree bucket (Poisson(16): P(deg>64) ~ 1e-18)
#define PAD     76      // smem row stride: 304B, 16B-aligned

// ---- scratch: __device__ globals (referenced ONLY from device code) ----
__device__ int    d_cnt[N_NODES];
__device__ int    d_col[(size_t)N_NODES * CAP];
__device__ float  d_dinv[N_NODES];
__device__ float2 d_pg[N_NODES];                     // x[n] * dinv[n]
__device__ float2 d_A1[N_NODES];                     // layer-1 aggregated 2-wide features
__device__ float  d_g1[(size_t)N_NODES * HID];       // relu(A1@W1+b1)*dinv
__device__ float  d_Wc[HID * HID + HID];             // W2@Wfc, then bc = b2@Wfc+bfc

// bucket edges by destination: 2 edges/thread, one int atomic each
__global__ void k_fill(const int* __restrict__ ei) {
    int t = blockIdx.x * blockDim.x + threadIdx.x;
    if (t >= N_EDGES / 2) return;
    int2 s2 = ((const int2*)ei)[t];
    int2 d2 = ((const int2*)(ei + N_EDGES))[t];
    int p0 = atomicAdd(&d_cnt[d2.x], 1);
    if (p0 < CAP) d_col[d2.x * CAP + p0] = s2.x;
    int p1 = atomicAdd(&d_cnt[d2.y], 1);
    if (p1 < CAP) d_col[d2.y * CAP + p1] = s2.y;
}

// precompute Wc = W2 @ Wfc and bc = b2 @ Wfc + bfc
__global__ void k_wc(const float* __restrict__ W2, const float* __restrict__ b2,
                     const float* __restrict__ Wfc, const float* __restrict__ bfc) {
    int t = blockIdx.x * blockDim.x + threadIdx.x;
    if (t < HID * HID) {
        int k = t >> 6, c = t & 63;
        float o = 0.0f;
#pragma unroll 16
        for (int j = 0; j < HID; j++) o += W2[k * HID + j] * Wfc[j * HID + c];
        d_Wc[t] = o;
    } else if (t < HID * HID + HID) {
        int c = t - HID * HID;
        float o = bfc[c];
#pragma unroll 16
        for (int j = 0; j < HID; j++) o += b2[j] * Wfc[j * HID + c];
        d_Wc[HID * HID + c] = o;
    }
}

// per node: dinv and pg = x * dinv
__global__ void k_prep(const float2* __restrict__ x) {
    int n = blockIdx.x * blockDim.x + threadIdx.x;
    if (n >= N_NODES) return;
    float di = rsqrtf((float)d_cnt[n] + 1.0f);
    d_dinv[n] = di;
    float2 xv = __ldg(&x[n]);
    d_pg[n] = make_float2(xv.x * di, xv.y * di);
}

// layer-1 aggregation on raw 2-wide features: A1 = dinv*(sum pg[src] + pg[n])
__global__ void k_agg1() {
    int n = blockIdx.x * blockDim.x + threadIdx.x;
    if (n >= N_NODES) return;
    int deg = d_cnt[n];
    if (deg > CAP) deg = CAP;
    const int* cl = &d_col[n * CAP];
    float ax = 0.0f, ay = 0.0f;
    int e = 0;
    for (; e + 8 <= deg; e += 8) {
        int4 i0 = *(const int4*)&cl[e];
        int4 i1 = *(const int4*)&cl[e + 4];
        float2 p0 = d_pg[i0.x], p1 = d_pg[i0.y], p2 = d_pg[i0.z], p3 = d_pg[i0.w];
        float2 p4 = d_pg[i1.x], p5 = d_pg[i1.y], p6 = d_pg[i1.z], p7 = d_pg[i1.w];
        ax += ((p0.x + p1.x) + (p2.x + p3.x)) + ((p4.x + p5.x) + (p6.x + p7.x));
        ay += ((p0.y + p1.y) + (p2.y + p3.y)) + ((p4.y + p5.y) + (p6.y + p7.y));
    }
    for (; e < deg; e++) {
        float2 p = d_pg[cl[e]];
        ax += p.x; ay += p.y;
    }
    float di = d_dinv[n];
    float2 pn = d_pg[n];
    ax = di * (ax + pn.x);
    ay = di * (ay + pn.y);
    d_A1[n] = make_float2(ax, ay);
}

// g1 = relu(A1 @ W1 + b1) * dinv
__global__ void k_h1(const float* __restrict__ W1, const float* __restrict__ b1) {
    int idx = blockIdx.x * blockDim.x + threadIdx.x;
    if (idx >= N_NODES * 16) return;
    int n = idx >> 4, q = idx & 15;
    float2 A = d_A1[n];
    float di = d_dinv[n];
    const float4* W1v = (const float4*)W1;
    float4 w0 = __ldg(&W1v[q]);
    float4 w1 = __ldg(&W1v[16 + q]);
    float4 bv = __ldg(&((const float4*)b1)[q]);
    float4 g;
    g.x = fmaxf(A.x * w0.x + A.y * w1.x + bv.x, 0.0f) * di;
    g.y = fmaxf(A.x * w0.y + A.y * w1.y + bv.y, 0.0f) * di;
    g.z = fmaxf(A.x * w0.z + A.y * w1.z + bv.z, 0.0f) * di;
    g.w = fmaxf(A.x * w0.w + A.y * w1.w + bv.w, 0.0f) * di;
    ((float4*)d_g1)[idx] = g;
}

// layer-2 aggregation (64 nodes/block) + fused 4x4-register-tiled matmul
__global__ void __launch_bounds__(256) k_agg2(float* __restrict__ out) {
    __shared__ float sWT[HID][PAD];  // transposed Wc
    __shared__ float sR[64][PAD];    // aggregated rows; reused for outputs
    __shared__ float sBc[HID];

    int tid = threadIdx.x;           // 256 threads, 8 warps, 64 nodes/block
    for (int i = tid; i < HID * HID; i += 256) {
        int k = i >> 6, c = i & 63;
        sWT[c][k] = d_Wc[i];
    }
    if (tid < HID) sBc[tid] = d_Wc[HID * HID + tid];

    int warp = tid >> 5, lane = tid & 31;
    const float* __restrict__ g1 = d_g1;

#pragma unroll
    for (int rep = 0; rep < 8; rep++) {
        int nl = warp * 8 + rep;                 // 0..63
        int n  = blockIdx.x * 64 + nl;
        int deg = d_cnt[n];
        if (deg > CAP) deg = CAP;
        const int* cl = &d_col[n * CAP];
        int idx0 = cl[lane];                     // coalesced (all CAP slots exist)
        int idx1 = cl[lane + 32];
        float a0 = 0.0f, a1 = 0.0f;
        int e = 0;
        for (; e + 8 <= deg; e += 8) {           // 16 independent LDGs in flight
            int hsel = (e < 32) ? idx0 : idx1;
            int b = e & 31;
            int s0 = __shfl_sync(0xffffffffu, hsel, b);
            int s1 = __shfl_sync(0xffffffffu, hsel, b + 1);
            int s2 = __shfl_sync(0xffffffffu, hsel, b + 2);
            int s3 = __shfl_sync(0xffffffffu, hsel, b + 3);
            int s4 = __shfl_sync(0xffffffffu, hsel, b + 4);
            int s5 = __shfl_sync(0xffffffffu, hsel, b + 5);
            int s6 = __shfl_sync(0xffffffffu, hsel, b + 6);
            int s7 = __shfl_sync(0xffffffffu, hsel, b + 7);
            const float* p0 = g1 + (size_t)s0 * HID;
            const float* p1 = g1 + (size_t)s1 * HID;
            const float* p2 = g1 + (size_t)s2 * HID;
            const float* p3 = g1 + (size_t)s3 * HID;
            const float* p4 = g1 + (size_t)s4 * HID;
            const float* p5 = g1 + (size_t)s5 * HID;
            const float* p6 = g1 + (size_t)s6 * HID;
            const float* p7 = g1 + (size_t)s7 * HID;
            float v0a = p0[lane], v0b = p0[lane + 32];
            float v1a = p1[lane], v1b = p1[lane + 32];
            float v2a = p2[lane], v2b = p2[lane + 32];
            float v3a = p3[lane], v3b = p3[lane + 32];
            float v4a = p4[lane], v4b = p4[lane + 32];
            float v5a = p5[lane], v5b = p5[lane + 32];
            float v6a = p6[lane], v6b = p6[lane + 32];
            float v7a = p7[lane], v7b = p7[lane + 32];
            a0 += ((v0a + v1a) + (v2a + v3a)) + ((v4a + v5a) + (v6a + v7a));
            a1 += ((v0b + v1b) + (v2b + v3b)) + ((v4b + v5b) + (v6b + v7b));
        }
        for (; e < deg; e++) {
            int hsel = (e < 32) ? idx0 : idx1;
            int s = __shfl_sync(0xffffffffu, hsel, e & 31);
            const float* p = g1 + (size_t)s * HID;
            a0 += p[lane];
            a1 += p[lane + 32];
        }
        const float* gn = g1 + (size_t)n * HID;   // self-loop
        a0 += gn[lane];
        a1 += gn[lane + 32];
        float di = d_dinv[n];
        sR[nl][lane]      = a0 * di;
        sR[nl][lane + 32] = a1 * di;
    }
    __syncthreads();

    // matmul 4x4: m0 = tid&15 -> nodes m0+16i; c0 = (tid>>4)*4 -> cols c0..c0+3
    int m0 = tid & 15, c0 = (tid >> 4) << 2;
    float o[4][4];
#pragma unroll
    for (int i = 0; i < 4; i++)
#pragma unroll
        for (int j = 0; j < 4; j++) o[i][j] = 0.0f;
#pragma unroll
    for (int k = 0; k < HID; k += 4) {
        float4 r0 = *(const float4*)&sR[m0][k];
        float4 r1 = *(const float4*)&sR[m0 + 16][k];
        float4 r2 = *(const float4*)&sR[m0 + 32][k];
        float4 r3 = *(const float4*)&sR[m0 + 48][k];
        float4 w0 = *(const float4*)&sWT[c0][k];
        float4 w1 = *(const float4*)&sWT[c0 + 1][k];
        float4 w2 = *(const float4*)&sWT[c0 + 2][k];
        float4 w3 = *(const float4*)&sWT[c0 + 3][k];
        float4 rr[4] = {r0, r1, r2, r3};
        float4 ww[4] = {w0, w1, w2, w3};
#pragma unroll
        for (int i = 0; i < 4; i++)
#pragma unroll
            for (int j = 0; j < 4; j++)
                o[i][j] += rr[i].x * ww[j].x + rr[i].y * ww[j].y +
                           rr[i].z * ww[j].z + rr[i].w * ww[j].w;
    }
    float bb[4] = {sBc[c0], sBc[c0 + 1], sBc[c0 + 2], sBc[c0 + 3]};
    __syncthreads();                  // all reads of sR done -> safe to overwrite
#pragma unroll
    for (int i = 0; i < 4; i++) {
        float4 v;
        v.x = rintf(fmaxf(o[i][0] + bb[0], 0.0f));   // round-half-even == jnp.round
        v.y = rintf(fmaxf(o[i][1] + bb[1], 0.0f));
        v.z = rintf(fmaxf(o[i][2] + bb[2], 0.0f));
        v.w = rintf(fmaxf(o[i][3] + bb[3], 0.0f));
        *(float4*)&sR[m0 + 16 * i][c0] = v;
    }
    __syncthreads();

#pragma unroll
    for (int rep = 0; rep < 8; rep++) {
        int nl = warp * 8 + rep;
        size_t ob = ((size_t)blockIdx.x * 64 + nl) * HID;
        out[ob + lane]      = sR[nl][lane];
        out[ob + lane + 32] = sR[nl][lane + 32];
    }
}

extern "C" void kernel_launch(void* const* d_in, const int* in_sizes, int n_in,
                              void* d_out, int out_size) {
    const float* x   = (const float*)d_in[0];   // [200000, 2]
    const int*   ei  = (const int*)d_in[1];     // [2, 3200000]
    const float* W1  = (const float*)d_in[2];   // [2, 64]
    const float* b1  = (const float*)d_in[3];   // [64]
    const float* W2  = (const float*)d_in[4];   // [64, 64]
    const float* b2  = (const float*)d_in[5];   // [64]
    const float* Wfc = (const float*)d_in[6];   // [64, 64]
    const float* bfc = (const float*)d_in[7];   // [64]
    float* out = (float*)d_out;                 // [112000*64] flat

    void* cnt_addr = nullptr;
    cudaGetSymbolAddress(&cnt_addr, d_cnt);     // lookup only, no allocation
    cudaMemsetAsync(cnt_addr, 0, N_NODES * sizeof(int));

    k_wc<<<(HID * HID + HID + 255) / 256, 256>>>(W2, b2, Wfc, bfc);
    k_fill<<<(N_EDGES / 2 + 255) / 256, 256>>>(ei);
    k_prep<<<(N_NODES + 255) / 256, 256>>>((const float2*)x);
    k_agg1<<<(N_NODES + 255) / 256, 256>>>();
    k_h1<<<(N_NODES * 16 + 255) / 256, 256>>>(W1, b1);
    k_agg2<<<N_VAR / 64, 256>>>(out);
}